// round 15
// baseline (speedup 1.0000x reference)
#include <cuda_runtime.h>
#include <cuda_bf16.h>
#include <cuda_fp16.h>
#include <cstdint>

// Problem constants (fixed by the dataset)
#define K_DIM 256
#define N_DIM 64
#define MAX_NODES 100000
#define MAX_EDGES 1310720
#define SCAN_BLK 1024
#define MAX_SCAN_BLOCKS ((MAX_NODES + SCAN_BLK - 1) / SCAN_BLK + 2)

// Device scratch (no cudaMalloc allowed)
__device__ uint32_t g_pre_h[(size_t)MAX_NODES * 32];      // X@W as packed half2
// W pre-packed for the GEMM: per K-slab blob of u64 pairs
//   g_w_pk[s*1024 + (ks*4+t)*64 + q*8 + phys_j] =
//     ( tf32 w[s*32+ks*8+t][j*8+q], tf32 w[s*32+ks*8+t+4][j*8+q] ),
//   j = phys_j ^ (t<<1)   (swizzle for conflict-free LDS.128)
__device__ unsigned long long g_w_pk[8 * 1024];
__device__ int g_idx64;                                    // index dtype flag
__device__ int g_row_cnt[MAX_NODES];                       // counts, then cursor
__device__ int g_row_off[MAX_NODES + 1];                   // CSR offsets
__device__ unsigned long long g_edge_cv[MAX_EDGES];        // packed (val,col)
__device__ unsigned long long g_scan_state[MAX_SCAN_BLOCKS]; // lookback states

__device__ __forceinline__ int load_idx(const void* p, int e)
{
    return g_idx64 ? (int)((const long long*)p)[e] : ((const int*)p)[e];
}

__device__ __forceinline__ uint32_t f2tf32(float f)
{
    uint32_t r;
    asm("cvt.rna.tf32.f32 %0, %1;" : "=r"(r) : "f"(f));
    return r;
}

// ===========================================================================
// Fused init: block 0 = dtype detect + scan-state reset; blocks [1, zb] =
// zero g_row_cnt; blocks (zb, ...] = W pack (fp32 -> tf32 u64 pairs).
// ===========================================================================
__global__ void fused_init_kernel(const float* __restrict__ w,
                                  const unsigned int* __restrict__ rows_u32,
                                  int N, int E, int zb)
{
    int b = blockIdx.x;
    if (b == 0) {
        __shared__ int any;
        if (threadIdx.x == 0) any = 0;
        if (threadIdx.x < MAX_SCAN_BLOCKS) g_scan_state[threadIdx.x] = 0ull;
        __syncthreads();
        int n = E < 4096 ? E : 4096;
        for (int i = threadIdx.x; i < n; i += 256)
            if (rows_u32[2 * i + 1] != 0u) any = 1;   // benign smem race
        __syncthreads();
        if (threadIdx.x == 0) g_idx64 = any ? 0 : 1;
    } else if (b <= zb) {
        int i = (b - 1) * 256 + threadIdx.x;
        if (i < N) g_row_cnt[i] = 0;
    } else {
        int i = (b - 1 - zb) * 256 + threadIdx.x;   // 0..8191
        if (i < 8 * 1024) {
            int s  = i >> 10;
            int r  = i & 1023;
            int ks = r >> 8;
            int t  = (r >> 6) & 3;
            int q  = (r >> 3) & 7;
            int pj = r & 7;
            int j  = pj ^ (t << 1);
            int k0 = s * 32 + ks * 8 + t;
            int n  = j * 8 + q;
            uint32_t lo = f2tf32(w[(size_t)k0 * N_DIM + n]);
            uint32_t hi = f2tf32(w[(size_t)(k0 + 4) * N_DIM + n]);
            g_w_pk[i] = ((unsigned long long)hi << 32) | lo;
        }
    }
}

// ===========================================================================
// Fused GEMM + histogram. Blocks [0, GB): tf32 mma.sync GEMM tile, cp.async
// double-buffered; B frags read as LDS.128 from pre-packed W blobs.
// Blocks [GB, ...): row histogram (backfills SMs as GEMM CTAs retire).
// ===========================================================================
__device__ __forceinline__ uint32_t smem_u32(const void* p)
{
    uint32_t a;
    asm("{ .reg .u64 t; cvta.to.shared.u64 t, %1; cvt.u32.u64 %0, t; }"
        : "=r"(a) : "l"(p));
    return a;
}

__device__ __forceinline__ void mma_tf32(float* d, uint32_t a0, uint32_t a1,
                                         uint32_t a2, uint32_t a3,
                                         uint32_t b0, uint32_t b1)
{
    asm volatile(
        "mma.sync.aligned.m16n8k8.row.col.f32.tf32.tf32.f32 "
        "{%0, %1, %2, %3}, {%4, %5, %6, %7}, {%8, %9}, {%0, %1, %2, %3};"
        : "+f"(d[0]), "+f"(d[1]), "+f"(d[2]), "+f"(d[3])
        : "r"(a0), "r"(a1), "r"(a2), "r"(a3), "r"(b0), "r"(b1));
}

__device__ __forceinline__ void cp_async16(uint32_t dst, const void* src, int src_bytes)
{
    asm volatile("cp.async.cg.shared.global [%0], [%1], 16, %2;"
                 :: "r"(dst), "l"(src), "r"(src_bytes) : "memory");
}

__global__ void __launch_bounds__(256, 4) gemm_hist_kernel(
    const float* __restrict__ x, const void* __restrict__ rows_p,
    int M, int GB, int E)
{
    __shared__ float              xs[2][128 * 32];   // 2 x 16 KB
    __shared__ unsigned long long wsm[2][1024];      // 2 x  8 KB (packed pairs)

    // ---- histogram blocks
    if ((int)blockIdx.x >= GB) {
        int e = ((int)blockIdx.x - GB) * 256 + threadIdx.x;
        if (e < E) atomicAdd(&g_row_cnt[load_idx(rows_p, e)], 1);
        return;
    }

    // ---- GEMM blocks
    const int tid  = threadIdx.x;
    const int wid  = tid >> 5;
    const int lane = tid & 31;
    const int q = lane >> 2;
    const int t = lane & 3;

    const int mbase = blockIdx.x * 128;
    const int r0l = wid * 16 + q;
    const int r1l = r0l + 8;
    const int row0 = mbase + r0l;
    const int row1 = mbase + r1l;

    const uint32_t xs_base = smem_u32(&xs[0][0]);
    const uint32_t ws_base = smem_u32(&wsm[0][0]);

    float acc[8][4];
#pragma unroll
    for (int j = 0; j < 8; j++)
#pragma unroll
        for (int i = 0; i < 4; i++) acc[j][i] = 0.f;

    auto stage = [&](int s, int buf) {
#pragma unroll
        for (int i = 0; i < 4; i++) {           // X: 1024 x 16B chunks
            int f4 = i * 256 + tid;
            int m  = f4 >> 3;
            int c  = (f4 & 7) * 4;
            int phys = c ^ ((m & 7) * 4);
            uint32_t dst = xs_base + (uint32_t)(buf * (128 * 32) + m * 32 + phys) * 4u;
            const float* src = x + (size_t)(mbase + m) * K_DIM + s * 32 + c;
            cp_async16(dst, src, (mbase + m) < M ? 16 : 0);
        }
#pragma unroll
        for (int i = 0; i < 2; i++) {           // W blob: 512 x 16B chunks, linear
            int idx = i * 256 + tid;            // u64-pair index /2: 0..511
            uint32_t dst = ws_base + (uint32_t)(buf * 1024 + idx * 2) * 8u;
            cp_async16(dst, g_w_pk + (size_t)s * 1024 + idx * 2, 16);
        }
        asm volatile("cp.async.commit_group;" ::: "memory");
    };

    stage(0, 0);

#pragma unroll 1
    for (int s = 0; s < 8; s++) {
        if (s < 7) {
            stage(s + 1, (s + 1) & 1);
            asm volatile("cp.async.wait_group 1;" ::: "memory");
        } else {
            asm volatile("cp.async.wait_group 0;" ::: "memory");
        }
        __syncthreads();

        const float*              xb = xs[s & 1];
        const unsigned long long* wb = wsm[s & 1];
        const int swA = q * 4;

#pragma unroll
        for (int ks = 0; ks < 4; ks++) {
            const int kt = ks * 8 + t;
            uint32_t A0 = f2tf32(xb[r0l * 32 + (kt ^ swA)]);
            uint32_t A1 = f2tf32(xb[r1l * 32 + (kt ^ swA)]);
            uint32_t A2 = f2tf32(xb[r0l * 32 + ((kt + 4) ^ swA)]);
            uint32_t A3 = f2tf32(xb[r1l * 32 + ((kt + 4) ^ swA)]);
            const unsigned long long* wrow = wb + (ks * 4 + t) * 64 + q * 8;
#pragma unroll
            for (int jp = 0; jp < 4; jp++) {
                int phys = (2 * jp) ^ (t << 1);
                ulonglong2 bb = *(const ulonglong2*)(wrow + phys);
                mma_tf32(acc[2 * jp], A0, A1, A2, A3,
                         (uint32_t)bb.x, (uint32_t)(bb.x >> 32));
                mma_tf32(acc[2 * jp + 1], A0, A1, A2, A3,
                         (uint32_t)bb.y, (uint32_t)(bb.y >> 32));
            }
        }
        __syncthreads();
    }

    // ---- epilogue: pack adjacent cols (2t, 2t+1) into half2
#pragma unroll
    for (int j = 0; j < 8; j++) {
        int h_idx = j * 4 + t;
        if (row0 < M) {
            __half2 h = __float22half2_rn(make_float2(acc[j][0], acc[j][1]));
            g_pre_h[(size_t)row0 * 32 + h_idx] = *(uint32_t*)&h;
        }
        if (row1 < M) {
            __half2 h = __float22half2_rn(make_float2(acc[j][2], acc[j][3]));
            g_pre_h[(size_t)row1 * 32 + h_idx] = *(uint32_t*)&h;
        }
    }
}

// ===========================================================================
// Single-pass exclusive scan over g_row_cnt (decoupled lookback).
// Deadlock-free: block b only waits on blocks < b (launch-order progress).
// ===========================================================================
__global__ void __launch_bounds__(SCAN_BLK) scan_lookback_kernel(int N)
{
    __shared__ int warp_sums[32];
    __shared__ int s_prefix;
    const int b = blockIdx.x;
    const int idx = b * SCAN_BLK + threadIdx.x;
    const int lane = threadIdx.x & 31;
    const int wid  = threadIdx.x >> 5;

    int v = (idx < N) ? g_row_cnt[idx] : 0;
    int incl = v;
#pragma unroll
    for (int o = 1; o < 32; o <<= 1) {
        int n = __shfl_up_sync(0xffffffffu, incl, o);
        if (lane >= o) incl += n;
    }
    if (lane == 31) warp_sums[wid] = incl;
    __syncthreads();
    if (wid == 0) {
        int s = warp_sums[lane];
#pragma unroll
        for (int o = 1; o < 32; o <<= 1) {
            int n = __shfl_up_sync(0xffffffffu, s, o);
            if (lane >= o) s += n;
        }
        warp_sums[lane] = s;
    }
    __syncthreads();
    const int warp_base = (wid == 0) ? 0 : warp_sums[wid - 1];
    const int total = warp_sums[31];

    if (threadIdx.x == 0) {
        int run = 0;
        if (b == 0) {
            atomicExch(&g_scan_state[0], (2ull << 62) | (unsigned int)total);
        } else {
            atomicExch(&g_scan_state[b], (1ull << 62) | (unsigned int)total);
            int i = b - 1;
            for (;;) {
                unsigned long long st;
                do { st = atomicOr(&g_scan_state[i], 0ull); } while ((st >> 62) == 0);
                run += (int)(st & 0x7fffffffull);
                if ((st >> 62) == 2ull) break;
                i--;
            }
            atomicExch(&g_scan_state[b], (2ull << 62) | (unsigned int)(run + total));
        }
        s_prefix = run;
    }
    __syncthreads();

    int excl = s_prefix + warp_base + incl - v;
    if (idx < N) {
        g_row_off[idx] = excl;
        g_row_cnt[idx] = excl;            // becomes the permute cursor
        if (idx == N - 1) g_row_off[N] = excl + v;
    }
}

// ===========================================================================
// permute: scatter (col,val) into row-sorted list
// ===========================================================================
__global__ void permute_kernel(const void* __restrict__ rows_p,
                               const void* __restrict__ cols_p,
                               const float* __restrict__ vals, int E)
{
    int e = blockIdx.x * blockDim.x + threadIdx.x;
    if (e >= E) return;
    int r = load_idx(rows_p, e);
    int c = load_idx(cols_p, e);
    unsigned int v = __float_as_uint(vals[e]);
    int pos = atomicAdd(&g_row_cnt[r], 1);
    g_edge_cv[pos] = ((unsigned long long)v << 32) | (unsigned int)c;
}

// ===========================================================================
// Gather-reduce: out[r,:] = relu( sum_e val*pre_sup[col,:] + bias )
// 16 threads per row; pre_sup is packed half2 (8B per quad per edge).
// ===========================================================================
__global__ void __launch_bounds__(256) gather_kernel(
    const float* __restrict__ bias, float* __restrict__ out, int N)
{
    int r = blockIdx.x * 16 + (threadIdx.x >> 4);
    int q = threadIdx.x & 15;
    if (r >= N) return;

    int i   = g_row_off[r];
    int end = g_row_off[r + 1];

    float4 acc0 = make_float4(0.f, 0.f, 0.f, 0.f);
    float4 acc1 = make_float4(0.f, 0.f, 0.f, 0.f);
    for (; i + 2 <= end; i += 2) {
        unsigned long long cv0 = g_edge_cv[i];
        unsigned long long cv1 = g_edge_cv[i + 1];
        int c0 = (int)(unsigned int)cv0;
        int c1 = (int)(unsigned int)cv1;
        float v0 = __uint_as_float((unsigned int)(cv0 >> 32));
        float v1 = __uint_as_float((unsigned int)(cv1 >> 32));
        uint2 u0 = *(const uint2*)(g_pre_h + (size_t)c0 * 32 + q * 2);
        uint2 u1 = *(const uint2*)(g_pre_h + (size_t)c1 * 32 + q * 2);
        float2 p0a = __half22float2(*(__half2*)&u0.x);
        float2 p0b = __half22float2(*(__half2*)&u0.y);
        float2 p1a = __half22float2(*(__half2*)&u1.x);
        float2 p1b = __half22float2(*(__half2*)&u1.y);
        acc0.x = fmaf(v0, p0a.x, acc0.x);
        acc0.y = fmaf(v0, p0a.y, acc0.y);
        acc0.z = fmaf(v0, p0b.x, acc0.z);
        acc0.w = fmaf(v0, p0b.y, acc0.w);
        acc1.x = fmaf(v1, p1a.x, acc1.x);
        acc1.y = fmaf(v1, p1a.y, acc1.y);
        acc1.z = fmaf(v1, p1b.x, acc1.z);
        acc1.w = fmaf(v1, p1b.y, acc1.w);
    }
    if (i < end) {
        unsigned long long cv = g_edge_cv[i];
        int c   = (int)(unsigned int)cv;
        float v = __uint_as_float((unsigned int)(cv >> 32));
        uint2 u = *(const uint2*)(g_pre_h + (size_t)c * 32 + q * 2);
        float2 pa = __half22float2(*(__half2*)&u.x);
        float2 pb = __half22float2(*(__half2*)&u.y);
        acc0.x = fmaf(v, pa.x, acc0.x);
        acc0.y = fmaf(v, pa.y, acc0.y);
        acc0.z = fmaf(v, pb.x, acc0.z);
        acc0.w = fmaf(v, pb.y, acc0.w);
    }

    float4 b = *(const float4*)(bias + q * 4);
    float4 o;
    o.x = fmaxf(acc0.x + acc1.x + b.x, 0.f);
    o.y = fmaxf(acc0.y + acc1.y + b.y, 0.f);
    o.z = fmaxf(acc0.z + acc1.z + b.z, 0.f);
    o.w = fmaxf(acc0.w + acc1.w + b.w, 0.f);
    *(float4*)(out + (size_t)r * N_DIM + q * 4) = o;
}

// ===========================================================================
// Launch (5 kernels)
// Inputs: 0:x f32[N,256]  1:rows i32/i64[E]  2:cols i32/i64[E]
//         3:vals f32[E]   4:weight f32[256,64]  5:bias f32[64]
// Output: f32 [N, 64]
// ===========================================================================
extern "C" void kernel_launch(void* const* d_in, const int* in_sizes, int n_in,
                              void* d_out, int out_size)
{
    const float* x    = (const float*)d_in[0];
    const void*  rows = d_in[1];
    const void*  cols = d_in[2];
    const float* vals = (const float*)d_in[3];
    const float* w    = (const float*)d_in[4];
    const float* bias = (const float*)d_in[5];
    float*       out  = (float*)d_out;

    const int N = in_sizes[0] / K_DIM;
    const int E = in_sizes[1];
    const int scan_blocks = (N + SCAN_BLK - 1) / SCAN_BLK;
    const int zb = (N + 255) / 256;                 // zero blocks
    const int wb = (8 * 1024 + 255) / 256;          // W-pack blocks
    const int GB = (N + 127) / 128;                 // gemm blocks
    const int HB = (E + 255) / 256;                 // hist blocks

    fused_init_kernel<<<1 + zb + wb, 256>>>(w, (const unsigned int*)rows, N, E, zb);
    gemm_hist_kernel<<<GB + HB, 256>>>(x, rows, N, GB, E);
    scan_lookback_kernel<<<scan_blocks, SCAN_BLK>>>(N);
    permute_kernel<<<(E + 511) / 512, 512>>>(rows, cols, vals, E);
    gather_kernel<<<(N + 15) / 16, 256>>>(bias, out, N);
}

// round 17
// speedup vs baseline: 1.0085x; 1.0085x over previous
#include <cuda_runtime.h>
#include <cuda_bf16.h>
#include <cuda_fp16.h>
#include <cstdint>

// Problem constants (fixed by the dataset)
#define K_DIM 256
#define N_DIM 64
#define MAX_NODES 100000
#define MAX_EDGES 1310720
#define SCAN_BLK 1024
#define MAX_SCAN_BLOCKS ((MAX_NODES + SCAN_BLK - 1) / SCAN_BLK + 2)

// Device scratch (no cudaMalloc allowed)
__device__ uint32_t g_pre_h[(size_t)MAX_NODES * 32];      // X@W as packed half2
// W pre-packed for the GEMM: per K-slab blob of u64 pairs
//   g_w_pk[s*1024 + (ks*4+t)*64 + q*8 + phys_j] =
//     ( tf32 w[s*32+ks*8+t][j*8+q], tf32 w[s*32+ks*8+t+4][j*8+q] ),
//   j = phys_j ^ (t<<1)   (swizzle for conflict-free LDS.128)
__device__ unsigned long long g_w_pk[8 * 1024];
__device__ int g_idx64;                                    // index dtype flag
__device__ int g_row_cnt[MAX_NODES];                       // histogram counts
__device__ int g_row_off[MAX_NODES + 1];                   // CSR offsets
__device__ int g_edge_rank[MAX_EDGES];                     // rank of edge in its row
__device__ unsigned long long g_edge_cv[MAX_EDGES];        // packed (val,col)
__device__ unsigned long long g_scan_state[MAX_SCAN_BLOCKS]; // lookback states

__device__ __forceinline__ int load_idx(const void* p, int e)
{
    return g_idx64 ? (int)((const long long*)p)[e] : ((const int*)p)[e];
}

__device__ __forceinline__ uint32_t f2tf32(float f)
{
    uint32_t r;
    asm("cvt.rna.tf32.f32 %0, %1;" : "=r"(r) : "f"(f));
    return r;
}

// ===========================================================================
// Fused init: block 0 = dtype detect + scan-state reset; blocks [1, zb] =
// zero g_row_cnt; blocks (zb, ...] = W pack (fp32 -> tf32 u64 pairs).
// ===========================================================================
__global__ void fused_init_kernel(const float* __restrict__ w,
                                  const unsigned int* __restrict__ rows_u32,
                                  int N, int E, int zb)
{
    int b = blockIdx.x;
    if (b == 0) {
        __shared__ int any;
        if (threadIdx.x == 0) any = 0;
        if (threadIdx.x < MAX_SCAN_BLOCKS) g_scan_state[threadIdx.x] = 0ull;
        __syncthreads();
        int n = E < 4096 ? E : 4096;
        for (int i = threadIdx.x; i < n; i += 256)
            if (rows_u32[2 * i + 1] != 0u) any = 1;   // benign smem race
        __syncthreads();
        if (threadIdx.x == 0) g_idx64 = any ? 0 : 1;
    } else if (b <= zb) {
        int i = (b - 1) * 256 + threadIdx.x;
        if (i < N) g_row_cnt[i] = 0;
    } else {
        int i = (b - 1 - zb) * 256 + threadIdx.x;   // 0..8191
        if (i < 8 * 1024) {
            int s  = i >> 10;
            int r  = i & 1023;
            int ks = r >> 8;
            int t  = (r >> 6) & 3;
            int q  = (r >> 3) & 7;
            int pj = r & 7;
            int j  = pj ^ (t << 1);
            int k0 = s * 32 + ks * 8 + t;
            int n  = j * 8 + q;
            uint32_t lo = f2tf32(w[(size_t)k0 * N_DIM + n]);
            uint32_t hi = f2tf32(w[(size_t)(k0 + 4) * N_DIM + n]);
            g_w_pk[i] = ((unsigned long long)hi << 32) | lo;
        }
    }
}

// ===========================================================================
// Fused GEMM + histogram. Blocks [0, GB): tf32 mma.sync GEMM tile, cp.async
// double-buffered; B frags read as LDS.128 from pre-packed W blobs.
// Blocks [GB, ...): row histogram; ALSO records each edge's rank within its
// row (the atomicAdd return value) so permute needs no atomics.
// ===========================================================================
__device__ __forceinline__ uint32_t smem_u32(const void* p)
{
    uint32_t a;
    asm("{ .reg .u64 t; cvta.to.shared.u64 t, %1; cvt.u32.u64 %0, t; }"
        : "=r"(a) : "l"(p));
    return a;
}

__device__ __forceinline__ void mma_tf32(float* d, uint32_t a0, uint32_t a1,
                                         uint32_t a2, uint32_t a3,
                                         uint32_t b0, uint32_t b1)
{
    asm volatile(
        "mma.sync.aligned.m16n8k8.row.col.f32.tf32.tf32.f32 "
        "{%0, %1, %2, %3}, {%4, %5, %6, %7}, {%8, %9}, {%0, %1, %2, %3};"
        : "+f"(d[0]), "+f"(d[1]), "+f"(d[2]), "+f"(d[3])
        : "r"(a0), "r"(a1), "r"(a2), "r"(a3), "r"(b0), "r"(b1));
}

__device__ __forceinline__ void cp_async16(uint32_t dst, const void* src, int src_bytes)
{
    asm volatile("cp.async.cg.shared.global [%0], [%1], 16, %2;"
                 :: "r"(dst), "l"(src), "r"(src_bytes) : "memory");
}

__global__ void __launch_bounds__(256, 4) gemm_hist_kernel(
    const float* __restrict__ x, const void* __restrict__ rows_p,
    int M, int GB, int E)
{
    __shared__ float              xs[2][128 * 32];   // 2 x 16 KB
    __shared__ unsigned long long wsm[2][1024];      // 2 x  8 KB (packed pairs)

    // ---- histogram blocks (record rank = old count)
    if ((int)blockIdx.x >= GB) {
        int e = ((int)blockIdx.x - GB) * 256 + threadIdx.x;
        if (e < E)
            g_edge_rank[e] = atomicAdd(&g_row_cnt[load_idx(rows_p, e)], 1);
        return;
    }

    // ---- GEMM blocks
    const int tid  = threadIdx.x;
    const int wid  = tid >> 5;
    const int lane = tid & 31;
    const int q = lane >> 2;
    const int t = lane & 3;

    const int mbase = blockIdx.x * 128;
    const int r0l = wid * 16 + q;
    const int r1l = r0l + 8;
    const int row0 = mbase + r0l;
    const int row1 = mbase + r1l;

    const uint32_t xs_base = smem_u32(&xs[0][0]);
    const uint32_t ws_base = smem_u32(&wsm[0][0]);

    float acc[8][4];
#pragma unroll
    for (int j = 0; j < 8; j++)
#pragma unroll
        for (int i = 0; i < 4; i++) acc[j][i] = 0.f;

    auto stage = [&](int s, int buf) {
#pragma unroll
        for (int i = 0; i < 4; i++) {           // X: 1024 x 16B chunks
            int f4 = i * 256 + tid;
            int m  = f4 >> 3;
            int c  = (f4 & 7) * 4;
            int phys = c ^ ((m & 7) * 4);
            uint32_t dst = xs_base + (uint32_t)(buf * (128 * 32) + m * 32 + phys) * 4u;
            const float* src = x + (size_t)(mbase + m) * K_DIM + s * 32 + c;
            cp_async16(dst, src, (mbase + m) < M ? 16 : 0);
        }
#pragma unroll
        for (int i = 0; i < 2; i++) {           // W blob: 512 x 16B chunks, linear
            int idx = i * 256 + tid;
            uint32_t dst = ws_base + (uint32_t)(buf * 1024 + idx * 2) * 8u;
            cp_async16(dst, g_w_pk + (size_t)s * 1024 + idx * 2, 16);
        }
        asm volatile("cp.async.commit_group;" ::: "memory");
    };

    stage(0, 0);

#pragma unroll 1
    for (int s = 0; s < 8; s++) {
        if (s < 7) {
            stage(s + 1, (s + 1) & 1);
            asm volatile("cp.async.wait_group 1;" ::: "memory");
        } else {
            asm volatile("cp.async.wait_group 0;" ::: "memory");
        }
        __syncthreads();

        const float*              xb = xs[s & 1];
        const unsigned long long* wb = wsm[s & 1];
        const int swA = q * 4;

#pragma unroll
        for (int ks = 0; ks < 4; ks++) {
            const int kt = ks * 8 + t;
            uint32_t A0 = f2tf32(xb[r0l * 32 + (kt ^ swA)]);
            uint32_t A1 = f2tf32(xb[r1l * 32 + (kt ^ swA)]);
            uint32_t A2 = f2tf32(xb[r0l * 32 + ((kt + 4) ^ swA)]);
            uint32_t A3 = f2tf32(xb[r1l * 32 + ((kt + 4) ^ swA)]);
            const unsigned long long* wrow = wb + (ks * 4 + t) * 64 + q * 8;
#pragma unroll
            for (int jp = 0; jp < 4; jp++) {
                int phys = (2 * jp) ^ (t << 1);
                ulonglong2 bb = *(const ulonglong2*)(wrow + phys);
                mma_tf32(acc[2 * jp], A0, A1, A2, A3,
                         (uint32_t)bb.x, (uint32_t)(bb.x >> 32));
                mma_tf32(acc[2 * jp + 1], A0, A1, A2, A3,
                         (uint32_t)bb.y, (uint32_t)(bb.y >> 32));
            }
        }
        __syncthreads();
    }

    // ---- epilogue: pack adjacent cols (2t, 2t+1) into half2
#pragma unroll
    for (int j = 0; j < 8; j++) {
        int h_idx = j * 4 + t;
        if (row0 < M) {
            __half2 h = __float22half2_rn(make_float2(acc[j][0], acc[j][1]));
            g_pre_h[(size_t)row0 * 32 + h_idx] = *(uint32_t*)&h;
        }
        if (row1 < M) {
            __half2 h = __float22half2_rn(make_float2(acc[j][2], acc[j][3]));
            g_pre_h[(size_t)row1 * 32 + h_idx] = *(uint32_t*)&h;
        }
    }
}

// ===========================================================================
// Single-pass exclusive scan over g_row_cnt -> g_row_off (decoupled lookback).
// ===========================================================================
__global__ void __launch_bounds__(SCAN_BLK) scan_lookback_kernel(int N)
{
    __shared__ int warp_sums[32];
    __shared__ int s_prefix;
    const int b = blockIdx.x;
    const int idx = b * SCAN_BLK + threadIdx.x;
    const int lane = threadIdx.x & 31;
    const int wid  = threadIdx.x >> 5;

    int v = (idx < N) ? g_row_cnt[idx] : 0;
    int incl = v;
#pragma unroll
    for (int o = 1; o < 32; o <<= 1) {
        int n = __shfl_up_sync(0xffffffffu, incl, o);
        if (lane >= o) incl += n;
    }
    if (lane == 31) warp_sums[wid] = incl;
    __syncthreads();
    if (wid == 0) {
        int s = warp_sums[lane];
#pragma unroll
        for (int o = 1; o < 32; o <<= 1) {
            int n = __shfl_up_sync(0xffffffffu, s, o);
            if (lane >= o) s += n;
        }
        warp_sums[lane] = s;
    }
    __syncthreads();
    const int warp_base = (wid == 0) ? 0 : warp_sums[wid - 1];
    const int total = warp_sums[31];

    if (threadIdx.x == 0) {
        int run = 0;
        if (b == 0) {
            atomicExch(&g_scan_state[0], (2ull << 62) | (unsigned int)total);
        } else {
            atomicExch(&g_scan_state[b], (1ull << 62) | (unsigned int)total);
            int i = b - 1;
            for (;;) {
                unsigned long long st;
                do { st = atomicOr(&g_scan_state[i], 0ull); } while ((st >> 62) == 0);
                run += (int)(st & 0x7fffffffull);
                if ((st >> 62) == 2ull) break;
                i--;
            }
            atomicExch(&g_scan_state[b], (2ull << 62) | (unsigned int)(run + total));
        }
        s_prefix = run;
    }
    __syncthreads();

    int excl = s_prefix + warp_base + incl - v;
    if (idx < N) {
        g_row_off[idx] = excl;
        if (idx == N - 1) g_row_off[N] = excl + v;
    }
}

// ===========================================================================
// permute (atomic-free): pos = g_row_off[row] + precomputed rank.
// Store is fire-and-forget; no dependent atomic round-trip.
// ===========================================================================
__global__ void permute_kernel(const void* __restrict__ rows_p,
                               const void* __restrict__ cols_p,
                               const float* __restrict__ vals, int E)
{
    int e = blockIdx.x * blockDim.x + threadIdx.x;
    if (e >= E) return;
    int r = load_idx(rows_p, e);
    int c = load_idx(cols_p, e);
    unsigned int v = __float_as_uint(vals[e]);
    int pos = g_row_off[r] + g_edge_rank[e];
    g_edge_cv[pos] = ((unsigned long long)v << 32) | (unsigned int)c;
}

// ===========================================================================
// Gather-reduce: out[r,:] = relu( sum_e val*pre_sup[col,:] + bias )
// 16 threads per row; pre_sup is packed half2 (8B per quad per edge).
// ===========================================================================
__global__ void __launch_bounds__(256) gather_kernel(
    const float* __restrict__ bias, float* __restrict__ out, int N)
{
    int r = blockIdx.x * 16 + (threadIdx.x >> 4);
    int q = threadIdx.x & 15;
    if (r >= N) return;

    int i   = g_row_off[r];
    int end = g_row_off[r + 1];

    float4 acc0 = make_float4(0.f, 0.f, 0.f, 0.f);
    float4 acc1 = make_float4(0.f, 0.f, 0.f, 0.f);
    for (; i + 2 <= end; i += 2) {
        unsigned long long cv0 = g_edge_cv[i];
        unsigned long long cv1 = g_edge_cv[i + 1];
        int c0 = (int)(unsigned int)cv0;
        int c1 = (int)(unsigned int)cv1;
        float v0 = __uint_as_float((unsigned int)(cv0 >> 32));
        float v1 = __uint_as_float((unsigned int)(cv1 >> 32));
        uint2 u0 = *(const uint2*)(g_pre_h + (size_t)c0 * 32 + q * 2);
        uint2 u1 = *(const uint2*)(g_pre_h + (size_t)c1 * 32 + q * 2);
        float2 p0a = __half22float2(*(__half2*)&u0.x);
        float2 p0b = __half22float2(*(__half2*)&u0.y);
        float2 p1a = __half22float2(*(__half2*)&u1.x);
        float2 p1b = __half22float2(*(__half2*)&u1.y);
        acc0.x = fmaf(v0, p0a.x, acc0.x);
        acc0.y = fmaf(v0, p0a.y, acc0.y);
        acc0.z = fmaf(v0, p0b.x, acc0.z);
        acc0.w = fmaf(v0, p0b.y, acc0.w);
        acc1.x = fmaf(v1, p1a.x, acc1.x);
        acc1.y = fmaf(v1, p1a.y, acc1.y);
        acc1.z = fmaf(v1, p1b.x, acc1.z);
        acc1.w = fmaf(v1, p1b.y, acc1.w);
    }
    if (i < end) {
        unsigned long long cv = g_edge_cv[i];
        int c   = (int)(unsigned int)cv;
        float v = __uint_as_float((unsigned int)(cv >> 32));
        uint2 u = *(const uint2*)(g_pre_h + (size_t)c * 32 + q * 2);
        float2 pa = __half22float2(*(__half2*)&u.x);
        float2 pb = __half22float2(*(__half2*)&u.y);
        acc0.x = fmaf(v, pa.x, acc0.x);
        acc0.y = fmaf(v, pa.y, acc0.y);
        acc0.z = fmaf(v, pb.x, acc0.z);
        acc0.w = fmaf(v, pb.y, acc0.w);
    }

    float4 b = *(const float4*)(bias + q * 4);
    float4 o;
    o.x = fmaxf(acc0.x + acc1.x + b.x, 0.f);
    o.y = fmaxf(acc0.y + acc1.y + b.y, 0.f);
    o.z = fmaxf(acc0.z + acc1.z + b.z, 0.f);
    o.w = fmaxf(acc0.w + acc1.w + b.w, 0.f);
    *(float4*)(out + (size_t)r * N_DIM + q * 4) = o;
}

// ===========================================================================
// Launch (5 kernels; permute is node #4 -> profiled)
// Inputs: 0:x f32[N,256]  1:rows i32/i64[E]  2:cols i32/i64[E]
//         3:vals f32[E]   4:weight f32[256,64]  5:bias f32[64]
// Output: f32 [N, 64]
// ===========================================================================
extern "C" void kernel_launch(void* const* d_in, const int* in_sizes, int n_in,
                              void* d_out, int out_size)
{
    const float* x    = (const float*)d_in[0];
    const void*  rows = d_in[1];
    const void*  cols = d_in[2];
    const float* vals = (const float*)d_in[3];
    const float* w    = (const float*)d_in[4];
    const float* bias = (const float*)d_in[5];
    float*       out  = (float*)d_out;

    const int N = in_sizes[0] / K_DIM;
    const int E = in_sizes[1];
    const int scan_blocks = (N + SCAN_BLK - 1) / SCAN_BLK;
    const int zb = (N + 255) / 256;                 // zero blocks
    const int wb = (8 * 1024 + 255) / 256;          // W-pack blocks
    const int GB = (N + 127) / 128;                 // gemm blocks
    const int HB = (E + 255) / 256;                 // hist blocks

    fused_init_kernel<<<1 + zb + wb, 256>>>(w, (const unsigned int*)rows, N, E, zb);
    gemm_hist_kernel<<<GB + HB, 256>>>(x, rows, N, GB, E);
    scan_lookback_kernel<<<scan_blocks, SCAN_BLK>>>(N);
    permute_kernel<<<(E + 511) / 512, 512>>>(rows, cols, vals, E);
    gather_kernel<<<(N + 15) / 16, 256>>>(bias, out, N);
}